// round 17
// baseline (speedup 1.0000x reference)
#include <cuda_runtime.h>
#include <cuda_fp16.h>

#define TT   512
#define HH   50
#define NTH  672         // 3 groups x 224 (7 warps each)
#define NBAT 14          // per block: 5 + 5 + 4 across groups
#define KT   4           // k16 tiles: K=64 = [W_fp16(50) | pad(14)]
#define HTP  72          // fp16 per hT row (36 words -> all-distinct banks)

typedef unsigned int u32;

__device__ __forceinline__ float tanhap(float x) {
    float y; asm("tanh.approx.f32 %0, %1;" : "=f"(y) : "f"(x)); return y;
}
__device__ __forceinline__ float sigap(float x) {
    return fmaf(tanhap(0.5f * x), 0.5f, 0.5f);
}
__device__ __forceinline__ u32 pkhf(float a, float b) {
    u32 lo = (u32)__half_as_ushort(__float2half_rn(a));
    u32 hi = (u32)__half_as_ushort(__float2half_rn(b));
    return (hi << 16) | lo;
}
__device__ __forceinline__ void mma16816(float* d, const u32* a, u32 b0, u32 b1) {
    asm volatile(
        "mma.sync.aligned.m16n8k16.row.col.f32.f16.f16.f32 "
        "{%0,%1,%2,%3}, {%4,%5,%6,%7}, {%8,%9}, {%0,%1,%2,%3};"
        : "+f"(d[0]), "+f"(d[1]), "+f"(d[2]), "+f"(d[3])
        : "r"(a[0]), "r"(a[1]), "r"(a[2]), "r"(a[3]), "r"(b0), "r"(b1));
}

#define NBAR(id) asm volatile("bar.sync %0, 224;" :: "r"(id) : "memory")

// Permuted A element (fp16 W). mma row r -> gate s=(r%32)/8 of unit
// j = 8*(r/32) + (r%8); k<50 -> W[(s*50+j)*50+k], else 0.
__device__ __forceinline__ float wperm(const float* W, int r, int k) {
    int w = r >> 5, s = (r & 31) >> 3, g = r & 7;
    int j = 8 * w + g;
    if (j >= HH || k >= HH) return 0.f;
    return W[(s * HH + j) * HH + k];
}

// One group: NG real batches (cols NG..7 garbage, bounded, masked at output)
template<int NG, int BID>
__device__ __forceinline__ void run_group(
    __half (*hT)[8][HTP], float (*x_sm)[8], float (*fcb)[HH + 2],
    float* sink, int b0g, int ltid, int stag,
    const float* __restrict__ x,    const float* __restrict__ W_ih,
    const float* __restrict__ W_hh, const float* __restrict__ b_ih,
    const float* __restrict__ b_hh, const float* __restrict__ fc_w,
    const float* __restrict__ fc_b, float* __restrict__ out)
{
    const int lwid = ltid >> 5;
    const int lan  = ltid & 31;
    const int g    = lan >> 2;
    const int tg   = lan & 3;
    const int j    = 8 * lwid + g;       // unit; active if < 50
    const int n0   = 2 * tg;
    const bool cell = (j < HH);

    // ---- zero hT (both bufs) and x_sm (garbage cols stay 0 forever) ----
    for (int i = ltid; i < 2 * 8 * HTP / 2; i += 224)
        reinterpret_cast<u32*>(&hT[0][0][0])[i] = 0;
    for (int i = ltid; i < 64 * 8; i += 224) (&x_sm[0][0])[i] = 0.f;

    // ---- A fragments (fp16, permuted W), persistent in registers ----
    u32 A[2][KT][4];
    #pragma unroll
    for (int mi = 0; mi < 2; mi++) {
        int r_lo = (2 * lwid + mi) * 16 + g;
        #pragma unroll
        for (int kt = 0; kt < KT; kt++) {
            int ka = kt * 16 + 2 * tg;
            A[mi][kt][0] = pkhf(wperm(W_hh, r_lo,     ka),     wperm(W_hh, r_lo,     ka + 1));
            A[mi][kt][1] = pkhf(wperm(W_hh, r_lo + 8, ka),     wperm(W_hh, r_lo + 8, ka + 1));
            A[mi][kt][2] = pkhf(wperm(W_hh, r_lo,     ka + 8), wperm(W_hh, r_lo,     ka + 9));
            A[mi][kt][3] = pkhf(wperm(W_hh, r_lo + 8, ka + 8), wperm(W_hh, r_lo + 8, ka + 9));
        }
    }

    // ---- per-thread update constants for unit j ----
    float wxi = 0.f, wxf = 0.f, wxg = 0.f, wxo = 0.f;
    float bii = 0.f, bif = 0.f, big = 0.f, bio = 0.f;
    if (cell) {
        wxi = W_ih[j];          bii = b_ih[j]          + b_hh[j];
        wxf = W_ih[j + HH];     bif = b_ih[j + HH]     + b_hh[j + HH];
        wxg = W_ih[j + 2*HH];   big = b_ih[j + 2*HH]   + b_hh[j + 2*HH];
        wxo = W_ih[j + 3*HH];   bio = b_ih[j + 3*HH]   + b_hh[j + 3*HH];
    }
    float cc[2] = {0.f, 0.f}, hh[2] = {0.f, 0.f};

    __syncthreads();   // shared init done before groups diverge

    // ---- anti-phase stagger ----
    if (stag) {
        float d = b_hh[0];
        #pragma unroll 1
        for (int i = 0; i < stag; i++) d = fmaf(d, 1.0000001f, 1e-7f);
        if (d == -1e30f) *sink = d;   // never true; defeats DCE
    }

    // ================= recurrence =================
    #pragma unroll 1
    for (int t = 0; t < TT; t++) {
        const int tt = t & 63;
        if (tt == 0) {
            if (ltid < NG * 16) {
                int bb = ltid >> 4, qq = ltid & 15;
                float4 v = reinterpret_cast<const float4*>(x)
                               [(size_t)(b0g + bb) * 128 + (t >> 6) * 16 + qq];
                x_sm[qq * 4 + 0][bb] = v.x; x_sm[qq * 4 + 1][bb] = v.y;
                x_sm[qq * 4 + 2][bb] = v.z; x_sm[qq * 4 + 3][bb] = v.w;
            }
            NBAR(BID);
        }

        // ---- GEMM with dual accumulator pairs (2-deep mma chains) ----
        float d0a[4] = {0,0,0,0}, d0b[4] = {0,0,0,0};
        float d1a[4] = {0,0,0,0}, d1b[4] = {0,0,0,0};
        {
            const __half (*hb)[HTP] = hT[t & 1];
            #pragma unroll
            for (int kt = 0; kt < KT; kt++) {
                int kof = kt * 16 + 2 * tg;
                u32 b0 = *reinterpret_cast<const u32*>(&hb[g][kof]);
                u32 b1 = *reinterpret_cast<const u32*>(&hb[g][kof + 8]);
                float* p0 = (kt & 1) ? d0b : d0a;
                float* p1 = (kt & 1) ? d1b : d1a;
                mma16816(p0, A[0][kt], b0, b1);
                mma16816(p1, A[1][kt], b0, b1);
            }
        }

        // ---- in-register cell update; write h (fp16) into hT[next] ----
        if (cell) {
            __half (*hw)[HTP] = hT[(t + 1) & 1];
            float xv0 = x_sm[tt][n0], xv1 = x_sm[tt][n0 + 1];

            float I0 = (d0a[0] + d0b[0]) + fmaf(wxi, xv0, bii);
            float I1 = (d0a[1] + d0b[1]) + fmaf(wxi, xv1, bii);
            float F0 = (d0a[2] + d0b[2]) + fmaf(wxf, xv0, bif);
            float F1 = (d0a[3] + d0b[3]) + fmaf(wxf, xv1, bif);
            float G0 = (d1a[0] + d1b[0]) + fmaf(wxg, xv0, big);
            float G1 = (d1a[1] + d1b[1]) + fmaf(wxg, xv1, big);
            float O0 = (d1a[2] + d1b[2]) + fmaf(wxo, xv0, bio);
            float O1 = (d1a[3] + d1b[3]) + fmaf(wxo, xv1, bio);

            cc[0] = sigap(F0) * cc[0] + sigap(I0) * tanhap(G0);
            cc[1] = sigap(F1) * cc[1] + sigap(I1) * tanhap(G1);
            hh[0] = sigap(O0) * tanhap(cc[0]);
            hh[1] = sigap(O1) * tanhap(cc[1]);

            hw[n0][j]     = __float2half_rn(hh[0]);
            hw[n0 + 1][j] = __float2half_rn(hh[1]);
        }
        NBAR(BID);       // hT[next] complete
    }

    // ================= FC epilogue on exact fp32 h_T =================
    if (cell) {
        fcb[n0][j]     = hh[0];
        fcb[n0 + 1][j] = hh[1];
    }
    NBAR(BID);
    if (ltid < NG * 3) {
        int bb = ltid / 3, o = ltid % 3;
        float s = fc_b[o];
        #pragma unroll
        for (int k = 0; k < HH; k++) s += fcb[bb][k] * fc_w[o * HH + k];
        out[(size_t)(b0g + bb) * 3 + o] = s;
    }
}

__global__ void __launch_bounds__(NTH, 1)
lstm_mma(const float* __restrict__ x,    const float* __restrict__ W_ih,
         const float* __restrict__ W_hh, const float* __restrict__ b_ih,
         const float* __restrict__ b_hh, const float* __restrict__ fc_w,
         const float* __restrict__ fc_b, float* __restrict__ out)
{
    __shared__ __align__(16) __half hT[3][2][8][HTP];     // 6.9 KB
    __shared__ __align__(16) float x_sm[3][64][8];        // 6 KB
    __shared__ __align__(16) float fcb[3][8][HH + 2];     // 5 KB
    __shared__ float sink;

    const int tid = threadIdx.x;
    const int grp = tid / 224;
    const int lt  = tid - grp * 224;
    const int b0  = min((int)blockIdx.x * NBAT, 2048 - NBAT);

    if (grp == 0) {
        run_group<5, 1>(hT[0], x_sm[0], fcb[0], &sink, b0, lt, 0,
                        x, W_ih, W_hh, b_ih, b_hh, fc_w, fc_b, out);
    } else if (grp == 1) {
        run_group<5, 2>(hT[1], x_sm[1], fcb[1], &sink, b0 + 5, lt, 55,
                        x, W_ih, W_hh, b_ih, b_hh, fc_w, fc_b, out);
    } else {
        run_group<4, 3>(hT[2], x_sm[2], fcb[2], &sink, b0 + 10, lt, 110,
                        x, W_ih, W_hh, b_ih, b_hh, fc_w, fc_b, out);
    }
}

extern "C" void kernel_launch(void* const* d_in, const int* in_sizes, int n_in,
                              void* d_out, int out_size) {
    const float* x    = (const float*)d_in[0];
    const float* W_ih = (const float*)d_in[1];
    const float* W_hh = (const float*)d_in[2];
    const float* b_ih = (const float*)d_in[3];
    const float* b_hh = (const float*)d_in[4];
    const float* fc_w = (const float*)d_in[5];
    const float* fc_b = (const float*)d_in[6];
    lstm_mma<<<147, NTH>>>(x, W_ih, W_hh, b_ih, b_hh, fc_w, fc_b, (float*)d_out);
}